// round 16
// baseline (speedup 1.0000x reference)
#include <cuda_runtime.h>
#include <cuda_fp16.h>
#include <cstdint>

// AWQ dequant + fp16 mma.sync GEMM (fp32 accum), dtype-adaptive I/O.
// Out[M,N] = X[M,K] @ ((Wq - Z)*S) + bias
//
// Round-16: R15 proved ptxas already hoists fragment loads (identical ncu to
// R13) -> the limiter is the LDS-phase issue cost (64 LDS.32 x ~4cyc/warp/tile,
// lockstepped). Fix: ldmatrix. A via m8n8.x4 (layout unchanged), B via
// m8n8.x4.trans from plain row-major W16[k][n] (dequant de-interleaved).
// 64 LDS -> 16 LDSM per warp/tile. Everything else R13-identical.
//   launch 0: probe+bias  1: prep_x  2: dequant  3: gemm <- profiled

#define M_DIM 4096
#define K_DIM 4096
#define N_DIM 11008

#define BM 128
#define BN 256
#define BK 32
#define NT (K_DIM / BK)          // 128

#define SA  40                   // halfs per As row (BK + 8 pad)
#define SBH 264                  // halfs per Bs k-row (BN + 8 pad)
#define STAGES 4

#define A_STAGE_B (BM * SA * 2)              // 10240 B
#define B_STAGE_B (BK * SBH * 2)             // 16896 B
#define STAGE_B   (A_STAGE_B + B_STAGE_B)    // 27136 B
#define SMEM_TOTAL (STAGES * STAGE_B)        // 108544 B

// flags: [0] c0-is-scales  [1] x-is-f32 (also out)  [2] scales-is-f32  [3] bias-is-f32
__device__ int    g_flags[4];
__device__ __half g_W16[(size_t)K_DIM * N_DIM];   // 90.2 MB, plain [k][n]
__device__ __half g_X16[(size_t)M_DIM * K_DIM];   // 33.5 MB
__device__ __half g_bias16[N_DIM];

// ---------------- probe + bias prep (launch 0) ----------------
__device__ __forceinline__ int count_in_range(const float* p, float lo, float hi) {
    int cnt = 0;
    for (int i = 0; i < 64; i++) {
        float v = fabsf(p[i]);
        if (isfinite(v) && v >= lo && v <= hi) cnt++;
    }
    return cnt;
}

__global__ __launch_bounds__(256)
void probe_bias_kernel(const unsigned* c0, const void* c1v,
                       const float* x, const void* bias) {
    if (threadIdx.x == 0) {
        bool c0_is_zeros = true;
        for (int i = 0; i < 8; i++) if (c0[i] > 15u) c0_is_zeros = false;
        g_flags[0] = c0_is_zeros ? 0 : 1;
        const float* s = c0_is_zeros ? (const float*)c1v : (const float*)c0;
        g_flags[2] = (count_in_range(s, 5e-4f, 0.02f) >= 52) ? 1 : 0;
        g_flags[1] = (count_in_range(x, 1e-4f, 50.f) >= 52) ? 1 : 0;
        g_flags[3] = (count_in_range((const float*)bias, 1e-4f, 50.f) >= 52) ? 1 : 0;
    }
    __syncthreads();
    const int bias_f32 = g_flags[3];
    for (int i = threadIdx.x; i < N_DIM; i += 256)
        g_bias16[i] = bias_f32 ? __float2half(((const float*)bias)[i])
                               : ((const __half*)bias)[i];
}

// ---------------- prep_x (launch 1) ----------------
__global__ __launch_bounds__(256)
void prep_x_kernel(const void* xv) {
    size_t base = ((size_t)blockIdx.x * 256 + threadIdx.x) * 16;
    if (g_flags[1]) {
        const float4* src = (const float4*)((const float*)xv + base);
        float4 a = src[0], b = src[1], c = src[2], d = src[3];
        __half2* dst = (__half2*)(g_X16 + base);
        dst[0] = __floats2half2_rn(a.x, a.y);
        dst[1] = __floats2half2_rn(a.z, a.w);
        dst[2] = __floats2half2_rn(b.x, b.y);
        dst[3] = __floats2half2_rn(b.z, b.w);
        dst[4] = __floats2half2_rn(c.x, c.y);
        dst[5] = __floats2half2_rn(c.z, c.w);
        dst[6] = __floats2half2_rn(d.x, d.y);
        dst[7] = __floats2half2_rn(d.z, d.w);
    } else {
        const uint4* src = (const uint4*)((const __half*)xv + base);
        uint4 a = src[0], b = src[1];
        *(uint4*)(g_X16 + base)     = a;
        *(uint4*)(g_X16 + base + 8) = b;
    }
}

// ---------------- dequant (launch 2): plain row-major W16[k][n] ----------------
// Thread: 4 n-cols x (2 k-rows) x 2 kp groups. uint2 stores per k-row.
__global__ __launch_bounds__(256)
void dequant_kernel(const int* __restrict__ W, const void* c0, const void* c1) {
    const int n4 = (blockIdx.x * 256 + threadIdx.x) * 4;
    if (n4 >= N_DIM) return;
    const int kp0 = blockIdx.y;                     // 0..1023
    const void* zv = g_flags[0] ? c1 : c0;
    const void* sv = g_flags[0] ? c0 : c1;
    const int sc_f32 = g_flags[2];

    #pragma unroll
    for (int r = 0; r < 2; r++) {
        const int kp = kp0 + r * 1024;
        const int g  = kp >> 6;
        int4 q0 = *(const int4*)(W + (size_t)(2 * kp) * N_DIM + n4);
        int4 q1 = *(const int4*)(W + (size_t)(2 * kp + 1) * N_DIM + n4);
        int4 z4 = *(const int4*)((const int*)zv + (size_t)g * N_DIM + n4);
        __half s4[4];
        if (sc_f32) {
            float4 f = *(const float4*)((const float*)sv + (size_t)g * N_DIM + n4);
            s4[0] = __float2half(f.x); s4[1] = __float2half(f.y);
            s4[2] = __float2half(f.z); s4[3] = __float2half(f.w);
        } else {
            *(uint2*)s4 = *(const uint2*)((const __half*)sv + (size_t)g * N_DIM + n4);
        }
        __half w0[4], w1[4];
        w0[0] = __hmul(__hsub(__int2half_rn(q0.x), __int2half_rn(z4.x)), s4[0]);
        w0[1] = __hmul(__hsub(__int2half_rn(q0.y), __int2half_rn(z4.y)), s4[1]);
        w0[2] = __hmul(__hsub(__int2half_rn(q0.z), __int2half_rn(z4.z)), s4[2]);
        w0[3] = __hmul(__hsub(__int2half_rn(q0.w), __int2half_rn(z4.w)), s4[3]);
        w1[0] = __hmul(__hsub(__int2half_rn(q1.x), __int2half_rn(z4.x)), s4[0]);
        w1[1] = __hmul(__hsub(__int2half_rn(q1.y), __int2half_rn(z4.y)), s4[1]);
        w1[2] = __hmul(__hsub(__int2half_rn(q1.z), __int2half_rn(z4.z)), s4[2]);
        w1[3] = __hmul(__hsub(__int2half_rn(q1.w), __int2half_rn(z4.w)), s4[3]);
        *(uint2*)(g_W16 + (size_t)(2 * kp) * N_DIM + n4)     = *(const uint2*)w0;
        *(uint2*)(g_W16 + (size_t)(2 * kp + 1) * N_DIM + n4) = *(const uint2*)w1;
    }
}

// ---------------- GEMM (launch 3): 256 thr, ldmatrix fragment loads ----------------
__device__ __forceinline__ void mma_16816(float* d, const uint32_t* a, const uint32_t* b) {
    asm volatile(
        "mma.sync.aligned.m16n8k16.row.col.f32.f16.f16.f32 "
        "{%0,%1,%2,%3}, {%4,%5,%6,%7}, {%8,%9}, {%0,%1,%2,%3};\n"
        : "+f"(d[0]), "+f"(d[1]), "+f"(d[2]), "+f"(d[3])
        : "r"(a[0]), "r"(a[1]), "r"(a[2]), "r"(a[3]), "r"(b[0]), "r"(b[1]));
}

__device__ __forceinline__ void ldsm_x4(uint32_t* d, uint32_t addr) {
    asm volatile("ldmatrix.sync.aligned.m8n8.x4.shared.b16 {%0,%1,%2,%3}, [%4];"
                 : "=r"(d[0]), "=r"(d[1]), "=r"(d[2]), "=r"(d[3]) : "r"(addr));
}

__device__ __forceinline__ void ldsm_x4_trans(uint32_t& d0, uint32_t& d1,
                                              uint32_t& d2, uint32_t& d3, uint32_t addr) {
    asm volatile("ldmatrix.sync.aligned.m8n8.x4.trans.shared.b16 {%0,%1,%2,%3}, [%4];"
                 : "=r"(d0), "=r"(d1), "=r"(d2), "=r"(d3) : "r"(addr));
}

__global__ __launch_bounds__(256, 1)
void gemm_kernel(void* __restrict__ OutV)
{
    extern __shared__ __align__(16) char smem[];

    const int tid  = threadIdx.x;
    const int lane = tid & 31;
    const int wid  = tid >> 5;

    const int m0 = blockIdx.x * BM;   // M fastest -> B panel L2 reuse
    const int n0 = blockIdx.y * BN;

    // 2 x 4 warps of 64M x 64N
    const int warp_m   = wid >> 2;
    const int warp_n   = wid & 3;
    const int m_base_w = warp_m * 64;
    const int n_base_w = warp_n * 64;
    const int g4 = lane >> 2;
    const int t4 = lane & 3;

    // ldmatrix per-lane base offsets (halfs)
    // A (non-trans): lane -> row (lane&15), k-col block (lane>>4)*8
    const uint32_t a_lane = (uint32_t)((m_base_w + (lane & 15)) * SA + ((lane >> 4) << 3));
    // B (trans): lane -> k-row (lane&7), n-col block (lane>>3)*8
    const uint32_t b_lane = (uint32_t)((lane & 7) * SBH + n_base_w + ((lane >> 3) << 3));

    float acc[4][8][4];
    #pragma unroll
    for (int i = 0; i < 4; i++)
        #pragma unroll
        for (int j = 0; j < 8; j++)
            #pragma unroll
            for (int e = 0; e < 4; e++) acc[i][j][e] = 0.0f;

    const uint32_t sbase = (uint32_t)__cvta_generic_to_shared(smem);

    auto load_a = [&](int kt, int s) {
        uint32_t abase = sbase + s * STAGE_B;
        #pragma unroll
        for (int i = 0; i < 2; i++) {
            int c   = tid + i * 256;
            int row = c >> 2;
            int c16 = c & 3;
            const __half* src = g_X16 + (size_t)(m0 + row) * K_DIM + kt * BK + c16 * 8;
            uint32_t dst = abase + (uint32_t)(row * SA + c16 * 8) * 2u;
            asm volatile("cp.async.cg.shared.global [%0], [%1], 16;" :: "r"(dst), "l"(src));
        }
    };

    auto load_b = [&](int kt, int s) {
        uint32_t bbase = sbase + s * STAGE_B + A_STAGE_B;
        #pragma unroll
        for (int i = 0; i < 4; i++) {
            int c   = tid + i * 256;     // 0..1023
            int row = c >> 5;            // k row 0..31
            int j   = c & 31;            // 16B chunk
            const __half* src = g_W16 + (size_t)(kt * BK + row) * N_DIM + n0 + j * 8;
            uint32_t dst = bbase + (uint32_t)(row * SBH + j * 8) * 2u;
            asm volatile("cp.async.cg.shared.global [%0], [%1], 16;" :: "r"(dst), "l"(src));
        }
    };

    auto compute = [&](int s) {
        uint32_t abase = sbase + s * STAGE_B;
        uint32_t bbase = abase + A_STAGE_B;
        uint32_t af[2][4][4];
        uint32_t bf[2][8][2];
        #pragma unroll
        for (int h = 0; h < 2; h++) {
            // A: one ldmatrix.x4 per 16x16 block (mt)
            #pragma unroll
            for (int mt = 0; mt < 4; mt++) {
                uint32_t addr = abase + (a_lane + (uint32_t)(mt * 16 * SA + h * 16)) * 2u;
                ldsm_x4(af[h][mt], addr);
            }
            // B: trans; (j = k8 block -> reg index, g = nt group of 4)
            #pragma unroll
            for (int j = 0; j < 2; j++) {
                #pragma unroll
                for (int g = 0; g < 2; g++) {
                    uint32_t addr = bbase +
                        (b_lane + (uint32_t)((h * 16 + j * 8) * SBH + g * 32)) * 2u;
                    ldsm_x4_trans(bf[h][g * 4 + 0][j], bf[h][g * 4 + 1][j],
                                  bf[h][g * 4 + 2][j], bf[h][g * 4 + 3][j], addr);
                }
            }
        }
        #pragma unroll
        for (int h = 0; h < 2; h++)
            #pragma unroll
            for (int mt = 0; mt < 4; mt++)
                #pragma unroll
                for (int nt = 0; nt < 8; nt++)
                    mma_16816(acc[mt][nt], af[h][mt], bf[h][nt]);
    };

    // ---- prologue: fill stages 0..2 ----
    #pragma unroll
    for (int p = 0; p < 3; p++) {
        load_a(p, p);
        load_b(p, p);
        asm volatile("cp.async.commit_group;");
    }

    // ---- mainloop: 4-stage ring, prefetch distance 3 ----
    for (int kt = 0; kt < NT; kt++) {
        if (kt < NT - 2)       asm volatile("cp.async.wait_group 2;" ::: "memory");
        else if (kt == NT - 2) asm volatile("cp.async.wait_group 1;" ::: "memory");
        else                   asm volatile("cp.async.wait_group 0;" ::: "memory");
        __syncthreads();
        if (kt + 3 < NT) {
            load_a(kt + 3, (kt + 3) & 3);
            load_b(kt + 3, (kt + 3) & 3);
            asm volatile("cp.async.commit_group;");
        }
        compute(kt & 3);
    }

    // ---- epilogue: fp16 round + fp16 bias add, widen iff fp32 out ----
    const int out_f32 = g_flags[1];
    #pragma unroll
    for (int mt = 0; mt < 4; mt++) {
        #pragma unroll
        for (int nt = 0; nt < 8; nt++) {
            int row = m0 + m_base_w + mt * 16 + g4;
            int col = n0 + n_base_w + nt * 8 + 2 * t4;
            __half2 bias2 = *(const __half2*)&g_bias16[col];
            __half2 r01 = __hadd2(__floats2half2_rn(acc[mt][nt][0], acc[mt][nt][1]), bias2);
            __half2 r23 = __hadd2(__floats2half2_rn(acc[mt][nt][2], acc[mt][nt][3]), bias2);
            if (out_f32) {
                float* O = (float*)OutV;
                *(float2*)&O[(size_t)row * N_DIM + col] =
                    make_float2(__half2float(__low2half(r01)), __half2float(__high2half(r01)));
                *(float2*)&O[(size_t)(row + 8) * N_DIM + col] =
                    make_float2(__half2float(__low2half(r23)), __half2float(__high2half(r23)));
            } else {
                __half* O = (__half*)OutV;
                *(__half2*)&O[(size_t)row * N_DIM + col] = r01;
                *(__half2*)&O[(size_t)(row + 8) * N_DIM + col] = r23;
            }
        }
    }
}

// ---------------- launch ----------------
extern "C" void kernel_launch(void* const* d_in, const int* in_sizes, int n_in,
                              void* d_out, int out_size) {
    int idx_x = 0, idx_w = 1, idx_b = 4, idx_zs0 = 2, idx_zs1 = 3;
    int zs_found = 0;
    for (int i = 0; i < n_in; i++) {
        int s = in_sizes[i];
        if (s == M_DIM * K_DIM)  idx_x = i;
        else if (s == 45088768)  idx_w = i;
        else if (s == N_DIM)     idx_b = i;
        else if (s == 352256) { if (zs_found == 0) idx_zs0 = i; else idx_zs1 = i; zs_found++; }
    }

    const void* x    = d_in[idx_x];
    const int*  w    = (const int*)d_in[idx_w];
    const void* c0   = d_in[idx_zs0];
    const void* c1   = d_in[idx_zs1];
    const void* bias = d_in[idx_b];

    probe_bias_kernel<<<1, 256>>>((const unsigned*)c0, c1, (const float*)x, bias);
    prep_x_kernel<<<(M_DIM * (size_t)K_DIM) / (256 * 16), 256>>>(x);

    dim3 dq_grid((N_DIM / 4 + 255) / 256, K_DIM / 4);    // (11, 1024)
    dequant_kernel<<<dq_grid, 256>>>(w, c0, c1);

    cudaFuncSetAttribute(gemm_kernel, cudaFuncAttributeMaxDynamicSharedMemorySize, SMEM_TOTAL);
    dim3 grid(M_DIM / BM, N_DIM / BN);                   // (32, 43), M fastest
    gemm_kernel<<<grid, 256, SMEM_TOTAL>>>(d_out);
}

// round 17
// speedup vs baseline: 1.2162x; 1.2162x over previous
#include <cuda_runtime.h>
#include <cuda_fp16.h>
#include <cstdint>

// AWQ dequant + fp16 mma.sync GEMM (fp32 accum), dtype-adaptive I/O.
// Out[M,N] = X[M,K] @ ((Wq - Z)*S) + bias
//
// Round-17: ldmatrix (R16) and ILP-reorder (R15) both left tensor ~50% ->
// limiter is phase lockstep: 1 CTA/SM means every warp does LDS-phase then
// MMA-phase in sync behind each tile barrier. Fix: 2 CTAs/SM, desynced, so
// phases overlap. Per-warp tile 64x32 (R3-proven map) + launch_bounds(256,2)
// keeps natural reg demand ~130 -> cap 128 without mainloop spills.
//   launch 0: probe+bias  1: prep_x  2: dequant(kp-interleaved)  3: gemm

#define M_DIM 4096
#define K_DIM 4096
#define N_DIM 11008
#define KP_DIM (K_DIM / 2)

#define BM 128
#define BN 128
#define BK 32
#define NT (K_DIM / BK)          // 128

#define SA  40                   // halfs per As row (BK + 8 pad)
#define SB2 136                  // half2 per Bs kp-row (BN + 8 pad)
#define STAGES 4

#define A_STAGE_B (BM * SA * 2)              // 10240 B
#define B_STAGE_B ((BK / 2) * SB2 * 4)       // 8704 B
#define STAGE_B   (A_STAGE_B + B_STAGE_B)    // 18944 B
#define SMEM_TOTAL (STAGES * STAGE_B)        // 75776 B (x2 CTAs = 151.5 KB)

// flags: [0] c0-is-scales  [1] x-is-f32 (also out)  [2] scales-is-f32  [3] bias-is-f32
__device__ int     g_flags[4];
__device__ __half2 g_Wd[(size_t)KP_DIM * N_DIM];   // 90.2 MB, k-pair interleaved
__device__ __half  g_X16[(size_t)M_DIM * K_DIM];   // 33.5 MB
__device__ __half  g_bias16[N_DIM];

// ---------------- probe + bias prep (launch 0) ----------------
__device__ __forceinline__ int count_in_range(const float* p, float lo, float hi) {
    int cnt = 0;
    for (int i = 0; i < 64; i++) {
        float v = fabsf(p[i]);
        if (isfinite(v) && v >= lo && v <= hi) cnt++;
    }
    return cnt;
}

__global__ __launch_bounds__(256)
void probe_bias_kernel(const unsigned* c0, const void* c1v,
                       const float* x, const void* bias) {
    if (threadIdx.x == 0) {
        bool c0_is_zeros = true;
        for (int i = 0; i < 8; i++) if (c0[i] > 15u) c0_is_zeros = false;
        g_flags[0] = c0_is_zeros ? 0 : 1;
        const float* s = c0_is_zeros ? (const float*)c1v : (const float*)c0;
        g_flags[2] = (count_in_range(s, 5e-4f, 0.02f) >= 52) ? 1 : 0;
        g_flags[1] = (count_in_range(x, 1e-4f, 50.f) >= 52) ? 1 : 0;
        g_flags[3] = (count_in_range((const float*)bias, 1e-4f, 50.f) >= 52) ? 1 : 0;
    }
    __syncthreads();
    const int bias_f32 = g_flags[3];
    for (int i = threadIdx.x; i < N_DIM; i += 256)
        g_bias16[i] = bias_f32 ? __float2half(((const float*)bias)[i])
                               : ((const __half*)bias)[i];
}

// ---------------- prep_x (launch 1) ----------------
__global__ __launch_bounds__(256)
void prep_x_kernel(const void* xv) {
    size_t base = ((size_t)blockIdx.x * 256 + threadIdx.x) * 16;
    if (g_flags[1]) {
        const float4* src = (const float4*)((const float*)xv + base);
        float4 a = src[0], b = src[1], c = src[2], d = src[3];
        __half2* dst = (__half2*)(g_X16 + base);
        dst[0] = __floats2half2_rn(a.x, a.y);
        dst[1] = __floats2half2_rn(a.z, a.w);
        dst[2] = __floats2half2_rn(b.x, b.y);
        dst[3] = __floats2half2_rn(b.z, b.w);
        dst[4] = __floats2half2_rn(c.x, c.y);
        dst[5] = __floats2half2_rn(c.z, c.w);
        dst[6] = __floats2half2_rn(d.x, d.y);
        dst[7] = __floats2half2_rn(d.z, d.w);
    } else {
        const uint4* src = (const uint4*)((const __half*)xv + base);
        uint4 a = src[0], b = src[1];
        *(uint4*)(g_X16 + base)     = a;
        *(uint4*)(g_X16 + base + 8) = b;
    }
}

// ---------------- dequant v2 (launch 2): kp-interleaved g_Wd ----------------
__global__ __launch_bounds__(256)
void dequant_kernel(const int* __restrict__ W, const void* c0, const void* c1) {
    const int n4 = (blockIdx.x * 256 + threadIdx.x) * 4;
    if (n4 >= N_DIM) return;
    const int kp0 = blockIdx.y;                     // 0..1023
    const void* zv = g_flags[0] ? c1 : c0;
    const void* sv = g_flags[0] ? c0 : c1;
    const int sc_f32 = g_flags[2];

    #pragma unroll
    for (int r = 0; r < 2; r++) {
        const int kp = kp0 + r * 1024;
        const int g  = kp >> 6;
        int4 q0 = *(const int4*)(W + (size_t)(2 * kp) * N_DIM + n4);
        int4 q1 = *(const int4*)(W + (size_t)(2 * kp + 1) * N_DIM + n4);
        int4 z4 = *(const int4*)((const int*)zv + (size_t)g * N_DIM + n4);
        __half s4[4];
        if (sc_f32) {
            float4 f = *(const float4*)((const float*)sv + (size_t)g * N_DIM + n4);
            s4[0] = __float2half(f.x); s4[1] = __float2half(f.y);
            s4[2] = __float2half(f.z); s4[3] = __float2half(f.w);
        } else {
            *(uint2*)s4 = *(const uint2*)((const __half*)sv + (size_t)g * N_DIM + n4);
        }
        __half2 w[4];
        w[0] = __hmul2(__hsub2(__halves2half2(__int2half_rn(q0.x), __int2half_rn(q1.x)),
                               __half2half2(__int2half_rn(z4.x))), __half2half2(s4[0]));
        w[1] = __hmul2(__hsub2(__halves2half2(__int2half_rn(q0.y), __int2half_rn(q1.y)),
                               __half2half2(__int2half_rn(z4.y))), __half2half2(s4[1]));
        w[2] = __hmul2(__hsub2(__halves2half2(__int2half_rn(q0.z), __int2half_rn(q1.z)),
                               __half2half2(__int2half_rn(z4.z))), __half2half2(s4[2]));
        w[3] = __hmul2(__hsub2(__halves2half2(__int2half_rn(q0.w), __int2half_rn(q1.w)),
                               __half2half2(__int2half_rn(z4.w))), __half2half2(s4[3]));
        *(uint4*)(g_Wd + (size_t)kp * N_DIM + n4) = *(const uint4*)&w[0];
    }
}

// ---------------- GEMM (launch 3): 256 thr, 2 CTAs/SM, 64x32 warp tiles ----------------
__device__ __forceinline__ void mma_16816(float* d, const uint32_t* a, const uint32_t* b) {
    asm volatile(
        "mma.sync.aligned.m16n8k16.row.col.f32.f16.f16.f32 "
        "{%0,%1,%2,%3}, {%4,%5,%6,%7}, {%8,%9}, {%0,%1,%2,%3};\n"
        : "+f"(d[0]), "+f"(d[1]), "+f"(d[2]), "+f"(d[3])
        : "r"(a[0]), "r"(a[1]), "r"(a[2]), "r"(a[3]), "r"(b[0]), "r"(b[1]));
}

__global__ __launch_bounds__(256, 2)
void gemm_kernel(void* __restrict__ OutV)
{
    extern __shared__ __align__(16) char smem[];

    const int tid  = threadIdx.x;
    const int lane = tid & 31;
    const int wid  = tid >> 5;

    const int m0 = blockIdx.x * BM;   // M fastest -> B panel L2 reuse
    const int n0 = blockIdx.y * BN;

    // 2 x 4 warps of 64M x 32N (R3-proven map)
    const int warp_m   = wid >> 2;
    const int warp_n   = wid & 3;
    const int m_base_w = warp_m * 64;
    const int n_base_w = warp_n * 32;
    const int g4 = lane >> 2;
    const int t4 = lane & 3;

    float acc[4][4][4];
    #pragma unroll
    for (int i = 0; i < 4; i++)
        #pragma unroll
        for (int j = 0; j < 4; j++)
            #pragma unroll
            for (int e = 0; e < 4; e++) acc[i][j][e] = 0.0f;

    const uint32_t sbase = (uint32_t)__cvta_generic_to_shared(smem);

    // A tile: 128 rows x 4 chunks(16B) = 512 chunks; 2 per thread
    auto load_a = [&](int kt, int s) {
        uint32_t abase = sbase + s * STAGE_B;
        #pragma unroll
        for (int i = 0; i < 2; i++) {
            int c   = tid + i * 256;
            int row = c >> 2;
            int c16 = c & 3;
            const __half* src = g_X16 + (size_t)(m0 + row) * K_DIM + kt * BK + c16 * 8;
            uint32_t dst = abase + (uint32_t)(row * SA + c16 * 8) * 2u;
            asm volatile("cp.async.cg.shared.global [%0], [%1], 16;" :: "r"(dst), "l"(src));
        }
    };

    // B tile: 16 kp-rows x 32 chunks(16B) = 512 chunks; 2 per thread
    auto load_b = [&](int kt, int s) {
        uint32_t bbase = sbase + s * STAGE_B + A_STAGE_B;
        #pragma unroll
        for (int i = 0; i < 2; i++) {
            int c  = tid + i * 256;
            int kp = c >> 5;                 // 0..15
            int j  = c & 31;                 // 16B chunk (4 half2)
            const __half2* src = g_Wd + (size_t)(kt * (BK / 2) + kp) * N_DIM + n0 + j * 4;
            uint32_t dst = bbase + (uint32_t)(kp * SB2 + j * 4) * 4u;
            asm volatile("cp.async.cg.shared.global [%0], [%1], 16;" :: "r"(dst), "l"(src));
        }
    };

    auto compute = [&](int s) {
        const __half*  As = (const __half*)(smem + s * STAGE_B);
        const __half2* Bs = (const __half2*)(smem + s * STAGE_B + A_STAGE_B);
        #pragma unroll
        for (int kk = 0; kk < BK; kk += 16) {
            uint32_t af[4][4];
            #pragma unroll
            for (int mt = 0; mt < 4; mt++) {
                const __half* base = &As[(m_base_w + mt * 16 + g4) * SA + kk + 2 * t4];
                af[mt][0] = *(const uint32_t*)(base);
                af[mt][1] = *(const uint32_t*)(base + 8 * SA);
                af[mt][2] = *(const uint32_t*)(base + 8);
                af[mt][3] = *(const uint32_t*)(base + 8 * SA + 8);
            }
            uint32_t bf[4][2];
            #pragma unroll
            for (int nt = 0; nt < 4; nt++) {
                const __half2* bb = &Bs[((kk >> 1) + t4) * SB2 + n_base_w + nt * 8 + g4];
                bf[nt][0] = *(const uint32_t*)(bb);
                bf[nt][1] = *(const uint32_t*)(bb + 4 * SB2);
            }
            #pragma unroll
            for (int mt = 0; mt < 4; mt++)
                #pragma unroll
                for (int nt = 0; nt < 4; nt++)
                    mma_16816(acc[mt][nt], af[mt], bf[nt]);
        }
    };

    // ---- prologue: fill stages 0..2 ----
    #pragma unroll
    for (int p = 0; p < 3; p++) {
        load_a(p, p);
        load_b(p, p);
        asm volatile("cp.async.commit_group;");
    }

    // ---- mainloop: 4-stage ring, prefetch distance 3 ----
    for (int kt = 0; kt < NT; kt++) {
        if (kt < NT - 2)       asm volatile("cp.async.wait_group 2;" ::: "memory");
        else if (kt == NT - 2) asm volatile("cp.async.wait_group 1;" ::: "memory");
        else                   asm volatile("cp.async.wait_group 0;" ::: "memory");
        __syncthreads();
        if (kt + 3 < NT) {
            load_a(kt + 3, (kt + 3) & 3);
            load_b(kt + 3, (kt + 3) & 3);
            asm volatile("cp.async.commit_group;");
        }
        compute(kt & 3);
    }

    // ---- epilogue: fp16 round + fp16 bias add, widen iff fp32 out ----
    const int out_f32 = g_flags[1];
    #pragma unroll
    for (int mt = 0; mt < 4; mt++) {
        #pragma unroll
        for (int nt = 0; nt < 4; nt++) {
            int row = m0 + m_base_w + mt * 16 + g4;
            int col = n0 + n_base_w + nt * 8 + 2 * t4;
            __half2 bias2 = *(const __half2*)&g_bias16[col];
            __half2 r01 = __hadd2(__floats2half2_rn(acc[mt][nt][0], acc[mt][nt][1]), bias2);
            __half2 r23 = __hadd2(__floats2half2_rn(acc[mt][nt][2], acc[mt][nt][3]), bias2);
            if (out_f32) {
                float* O = (float*)OutV;
                *(float2*)&O[(size_t)row * N_DIM + col] =
                    make_float2(__half2float(__low2half(r01)), __half2float(__high2half(r01)));
                *(float2*)&O[(size_t)(row + 8) * N_DIM + col] =
                    make_float2(__half2float(__low2half(r23)), __half2float(__high2half(r23)));
            } else {
                __half* O = (__half*)OutV;
                *(__half2*)&O[(size_t)row * N_DIM + col] = r01;
                *(__half2*)&O[(size_t)(row + 8) * N_DIM + col] = r23;
            }
        }
    }
}

// ---------------- launch ----------------
extern "C" void kernel_launch(void* const* d_in, const int* in_sizes, int n_in,
                              void* d_out, int out_size) {
    int idx_x = 0, idx_w = 1, idx_b = 4, idx_zs0 = 2, idx_zs1 = 3;
    int zs_found = 0;
    for (int i = 0; i < n_in; i++) {
        int s = in_sizes[i];
        if (s == M_DIM * K_DIM)  idx_x = i;
        else if (s == 45088768)  idx_w = i;
        else if (s == N_DIM)     idx_b = i;
        else if (s == 352256) { if (zs_found == 0) idx_zs0 = i; else idx_zs1 = i; zs_found++; }
    }

    const void* x    = d_in[idx_x];
    const int*  w    = (const int*)d_in[idx_w];
    const void* c0   = d_in[idx_zs0];
    const void* c1   = d_in[idx_zs1];
    const void* bias = d_in[idx_b];

    probe_bias_kernel<<<1, 256>>>((const unsigned*)c0, c1, (const float*)x, bias);
    prep_x_kernel<<<(M_DIM * (size_t)K_DIM) / (256 * 16), 256>>>(x);

    dim3 dq_grid((N_DIM / 4 + 255) / 256, KP_DIM / 2);   // (11, 1024)
    dequant_kernel<<<dq_grid, 256>>>(w, c0, c1);

    cudaFuncSetAttribute(gemm_kernel, cudaFuncAttributeMaxDynamicSharedMemorySize, SMEM_TOTAL);
    dim3 grid(M_DIM / BM, N_DIM / BN);                   // (32, 86), M fastest
    gemm_kernel<<<grid, 256, SMEM_TOTAL>>>(d_out);
}